// round 12
// baseline (speedup 1.0000x reference)
#include <cuda_runtime.h>
#include <cuda_fp16.h>
#include <math.h>
#include <stdint.h>

#define B 2
#define S 2048
#define D 768
#define H 12
#define E 64
#define BS (B*S)   // 4096
#define XN (BS*D)
#define HED (H*E*D)

#define LO_SCALE   2048.0f          // 2^11
#define LO_UNSCALE 4.8828125e-4f    // 2^-11

// ---- scratch (static device globals; no runtime allocation) ----
__device__ __align__(16) __half  g_x_hi[(size_t)BS * D];
__device__ __align__(16) uint8_t g_x_h8[(size_t)BS * D];      // e4m3(x)
__device__ __align__(16) uint8_t g_x_l8[(size_t)BS * D];      // e4m3((x - xh)*2^11)
__device__ __align__(16) __half  g_wt_hi[(size_t)3 * HED];    // [which][h*E+e][k]
__device__ __align__(16) uint8_t g_wt_h8[(size_t)3 * HED];
__device__ __align__(16) uint8_t g_wt_l8[(size_t)3 * HED];
__device__ __align__(16) __half  g_wo_hi[(size_t)D * D];      // [n][k]
__device__ __align__(16) __half  g_qkvb_hi[(size_t)3 * H * BS * E]; // q,k,v fp16
__device__ __align__(16) uint8_t g_q8[(size_t)H * BS * E];    // e4m3(q)
__device__ __align__(16) uint8_t g_kl8[(size_t)H * BS * E];   // e4m3((k - kh)*2^11)
__device__ __align__(16) __half  g_att_hi[(size_t)BS * D];

// ======================= helpers =======================
__device__ __forceinline__ uint32_t smem_u32(const void* p) {
    uint32_t a;
    asm("{ .reg .u64 t; cvta.to.shared.u64 t, %1; cvt.u32.u64 %0, t; }" : "=r"(a) : "l"(p));
    return a;
}
// swizzled offset, 128-byte rows (fp16 tiles): row r, 16B-chunk c16 (0..7)
__device__ __forceinline__ uint32_t sw_off(uint32_t r, uint32_t c16) {
    return (r << 7) + (((c16 ^ r) & 7u) << 4);
}
// swizzled offset, 64-byte rows (fp8 tiles): row r, 16B-chunk c (0..3)
// bank-group = (r*4 + (c ^ ((r>>1)&3))) mod 8 -> 8 distinct for any 8-row ldsm phase
__device__ __forceinline__ uint32_t sw8_off(uint32_t r, uint32_t c) {
    return (r << 6) + (((c ^ (r >> 1)) & 3u) << 4);
}
__device__ __forceinline__ void ldsm4(uint32_t* r, uint32_t a) {
    asm volatile("ldmatrix.sync.aligned.m8n8.x4.shared.b16 {%0,%1,%2,%3}, [%4];"
        : "=r"(r[0]), "=r"(r[1]), "=r"(r[2]), "=r"(r[3]) : "r"(a));
}
__device__ __forceinline__ void ldsm4t(uint32_t* r, uint32_t a) {
    asm volatile("ldmatrix.sync.aligned.m8n8.x4.trans.shared.b16 {%0,%1,%2,%3}, [%4];"
        : "=r"(r[0]), "=r"(r[1]), "=r"(r[2]), "=r"(r[3]) : "r"(a));
}
__device__ __forceinline__ void mma16816(float* c, const uint32_t* a, uint32_t b0, uint32_t b1) {
    asm volatile("mma.sync.aligned.m16n8k16.row.col.f32.f16.f16.f32 "
        "{%0,%1,%2,%3}, {%4,%5,%6,%7}, {%8,%9}, {%0,%1,%2,%3};"
        : "+f"(c[0]), "+f"(c[1]), "+f"(c[2]), "+f"(c[3])
        : "r"(a[0]), "r"(a[1]), "r"(a[2]), "r"(a[3]), "r"(b0), "r"(b1));
}
// fp8 e4m3 MMA, k=32 — fragments are b16-layout-compatible with fp16 ldmatrix
__device__ __forceinline__ void mma8(float* c, const uint32_t* a, uint32_t b0, uint32_t b1) {
    asm volatile("mma.sync.aligned.m16n8k32.row.col.f32.e4m3.e4m3.f32 "
        "{%0,%1,%2,%3}, {%4,%5,%6,%7}, {%8,%9}, {%0,%1,%2,%3};"
        : "+f"(c[0]), "+f"(c[1]), "+f"(c[2]), "+f"(c[3])
        : "r"(a[0]), "r"(a[1]), "r"(a[2]), "r"(a[3]), "r"(b0), "r"(b1));
}
__device__ __forceinline__ uint32_t pack2(float x, float y) {
    __half2 h = __floats2half2_rn(x, y);
    return *(uint32_t*)&h;
}
// pack 2 floats -> 2 e4m3 bytes (little-endian: byte0 = v0)
__device__ __forceinline__ uint16_t cvt2e4m3(float v0, float v1) {
    uint16_t r;
    asm("cvt.rn.satfinite.e4m3x2.f32 %0, %1, %2;" : "=h"(r) : "f"(v1), "f"(v0));
    return r;
}
#define CP_COMMIT()  asm volatile("cp.async.commit_group;" ::: "memory")
#define CP_WAIT1()   asm volatile("cp.async.wait_group 1;" ::: "memory")
#define CP_WAIT0()   asm volatile("cp.async.wait_group 0;" ::: "memory")

// cp.async R rows x 64 fp16 (128B/row) -> swizzled smem (256 threads)
template<int R>
__device__ __forceinline__ void cpa_tile(const __half* __restrict__ g, int ldg,
                                         uint32_t sdst, int t)
{
    #pragma unroll
    for (int i = 0; i < (R * 8) / 256; i++) {
        int f = i * 256 + t;
        uint32_t r = (uint32_t)(f >> 3), c = (uint32_t)(f & 7);
        asm volatile("cp.async.cg.shared.global [%0], [%1], 16;"
            :: "r"(sdst + sw_off(r, c)), "l"(g + (size_t)r * ldg + c * 8));
    }
}
// cp.async R rows x 64 fp8 (64B/row) -> swizzled smem (256 threads)
template<int R>
__device__ __forceinline__ void cpa_tile8(const uint8_t* __restrict__ g, int ldg,
                                          uint32_t sdst, int t)
{
    #pragma unroll
    for (int i = 0; i < (R * 4) / 256; i++) {
        int f = i * 256 + t;
        uint32_t r = (uint32_t)(f >> 2), c = (uint32_t)(f & 3);
        asm volatile("cp.async.cg.shared.global [%0], [%1], 16;"
            :: "r"(sdst + sw8_off(r, c)), "l"(g + (size_t)r * ldg + c * 16));
    }
}

// ======================= fused prep: fp32 -> fp16 + fp8 hi/lo =======================
__global__ void prep_kernel(const float* __restrict__ x,
                            const float* __restrict__ Wq, const float* __restrict__ Wk,
                            const float* __restrict__ Wv, const float* __restrict__ Wo)
{
    int i2 = (blockIdx.x * 256 + threadIdx.x) * 2;
    if (i2 < XN) {
        float v0 = x[i2], v1 = x[i2 + 1];
        uint32_t hp = pack2(v0, v1);
        *(uint32_t*)(g_x_hi + i2) = hp;
        *(uint16_t*)(g_x_h8 + i2) = cvt2e4m3(v0, v1);
        __half2 hh = *(__half2*)&hp;
        *(uint16_t*)(g_x_l8 + i2) = cvt2e4m3((v0 - __low2float(hh)) * LO_SCALE,
                                             (v1 - __high2float(hh)) * LO_SCALE);
    } else if (i2 < XN + 3 * HED) {
        int j = i2 - XN;
        int w = j / HED, r2 = j % HED;
        int k = r2 % D, row = r2 / D;
        int h = row / E, e = row % E;
        const float* W = (w == 0) ? Wq : (w == 1) ? Wk : Wv;
        float v0 = W[((size_t)h * D + k) * E + e];
        float v1 = W[((size_t)h * D + k + 1) * E + e];
        uint32_t hp = pack2(v0, v1);
        *(uint32_t*)(g_wt_hi + j) = hp;
        *(uint16_t*)(g_wt_h8 + j) = cvt2e4m3(v0, v1);
        __half2 hh = *(__half2*)&hp;
        *(uint16_t*)(g_wt_l8 + j) = cvt2e4m3((v0 - __low2float(hh)) * LO_SCALE,
                                             (v1 - __high2float(hh)) * LO_SCALE);
    } else if (i2 < XN + 3 * HED + D * D) {
        int j = i2 - XN - 3 * HED;
        int k = j % D, n = j / D;
        float v0 = Wo[(size_t)k * D + n];
        float v1 = Wo[(size_t)(k + 1) * D + n];
        *(uint32_t*)(g_wo_hi + j) = pack2(v0, v1);
    }
}

// ======================= GEMM passes: CTA 128x64, 8 warps (4x2), warp tile 32x32 ========
struct Acc64 { float a[2][4][4]; };
#define G_STAGE 24576   // fp16 pass: A 16K + B 8K ; fp8 pass: Ah 8K + Al 8K + Bh 4K + Bl 4K

// fp16 hi pass: C += A_hi * B_hi over 12 chunks of k64
__device__ __forceinline__ void gemm_fp16_pass(
    const __half* __restrict__ A_g, const __half* __restrict__ B_g, int lda, int ldb,
    uint32_t sb, int t, Acc64& C)
{
    const int lane = t & 31, wid = t >> 5;
    const int wm = (wid >> 1) * 32, wn = (wid & 1) * 32;

    cpa_tile<128>(A_g, lda, sb, t);
    cpa_tile<64>(B_g, ldb, sb + 16384, t);
    CP_COMMIT();

    const uint32_t a_row  = (uint32_t)(wm + (lane & 15));
    const uint32_t a_chi  = (uint32_t)((lane >> 4) & 1);
    const uint32_t b_row0 = (uint32_t)(wn + (lane & 7) + ((lane & 16) >> 1));
    const uint32_t b_chi  = (uint32_t)((lane >> 3) & 1);

    #pragma unroll 1
    for (int c = 0; c < 12; c++) {
        if (c + 1 < 12) {
            uint32_t st = sb + (uint32_t)((c + 1) & 1) * G_STAGE;
            cpa_tile<128>(A_g + (c + 1) * 64, lda, st, t);
            cpa_tile<64>(B_g + (c + 1) * 64, ldb, st + 16384, t);
            CP_COMMIT();
            CP_WAIT1();
        } else {
            CP_WAIT0();
        }
        __syncthreads();

        const uint32_t cs = sb + (uint32_t)(c & 1) * G_STAGE;
        const uint32_t uA = cs, uB = cs + 16384;

        #pragma unroll
        for (int ks = 0; ks < 4; ks++) {
            const uint32_t c16a = (uint32_t)(ks * 2) + a_chi;
            const uint32_t c16b = (uint32_t)(ks * 2) + b_chi;
            uint32_t ah0[4], ah1[4], bh0[4], bh1[4];
            ldsm4(ah0, uA + sw_off(a_row, c16a));
            ldsm4(ah1, uA + sw_off(a_row + 16, c16a));
            ldsm4(bh0, uB + sw_off(b_row0, c16b));
            ldsm4(bh1, uB + sw_off(b_row0 + 16, c16b));
            mma16816(C.a[0][0], ah0, bh0[0], bh0[1]);
            mma16816(C.a[0][1], ah0, bh0[2], bh0[3]);
            mma16816(C.a[1][0], ah1, bh0[0], bh0[1]);
            mma16816(C.a[1][1], ah1, bh0[2], bh0[3]);
            mma16816(C.a[0][2], ah0, bh1[0], bh1[1]);
            mma16816(C.a[0][3], ah0, bh1[2], bh1[3]);
            mma16816(C.a[1][2], ah1, bh1[0], bh1[1]);
            mma16816(C.a[1][3], ah1, bh1[2], bh1[3]);
        }
        __syncthreads();
    }
}

// fp8 cross pass: C += (A_lo8s * B_hi8) + (A_hi8 * B_lo8s)  [both scaled 2^11]
__device__ __forceinline__ void gemm_fp8_pass(
    const uint8_t* __restrict__ Ah_g, const uint8_t* __restrict__ Al_g,
    const uint8_t* __restrict__ Bh_g, const uint8_t* __restrict__ Bl_g,
    int lda, int ldb, uint32_t sb, int t, Acc64& C)
{
    const int lane = t & 31, wid = t >> 5;
    const int wm = (wid >> 1) * 32, wn = (wid & 1) * 32;

    cpa_tile8<128>(Ah_g, lda, sb, t);
    cpa_tile8<128>(Al_g, lda, sb + 8192, t);
    cpa_tile8<64>(Bh_g, ldb, sb + 16384, t);
    cpa_tile8<64>(Bl_g, ldb, sb + 20480, t);
    CP_COMMIT();

    const uint32_t a_row  = (uint32_t)(wm + (lane & 15));
    const uint32_t a_chi  = (uint32_t)((lane >> 4) & 1);
    const uint32_t b_row0 = (uint32_t)(wn + (lane & 7) + ((lane & 16) >> 1));
    const uint32_t b_chi  = (uint32_t)((lane >> 3) & 1);

    #pragma unroll 1
    for (int c = 0; c < 12; c++) {
        if (c + 1 < 12) {
            uint32_t st = sb + (uint32_t)((c + 1) & 1) * G_STAGE;
            cpa_tile8<128>(Ah_g + (c + 1) * 64, lda, st, t);
            cpa_tile8<128>(Al_g + (c + 1) * 64, lda, st + 8192, t);
            cpa_tile8<64>(Bh_g + (c + 1) * 64, ldb, st + 16384, t);
            cpa_tile8<64>(Bl_g + (c + 1) * 64, ldb, st + 20480, t);
            CP_COMMIT();
            CP_WAIT1();
        } else {
            CP_WAIT0();
        }
        __syncthreads();

        const uint32_t cs = sb + (uint32_t)(c & 1) * G_STAGE;
        const uint32_t uAh = cs, uAl = cs + 8192, uBh = cs + 16384, uBl = cs + 20480;

        #pragma unroll
        for (int ks = 0; ks < 2; ks++) {     // 2 k32 steps per k64 chunk
            const uint32_t ca = (uint32_t)(ks * 2) + a_chi;
            const uint32_t cb = (uint32_t)(ks * 2) + b_chi;
            uint32_t ah0[4], ah1[4], al0[4], al1[4];
            ldsm4(ah0, uAh + sw8_off(a_row, ca));
            ldsm4(ah1, uAh + sw8_off(a_row + 16, ca));
            ldsm4(al0, uAl + sw8_off(a_row, ca));
            ldsm4(al1, uAl + sw8_off(a_row + 16, ca));
            #pragma unroll
            for (int np = 0; np < 2; np++) {
                uint32_t bh[4], bl[4];
                ldsm4(bh, uBh + sw8_off(b_row0 + np * 16, cb));
                ldsm4(bl, uBl + sw8_off(b_row0 + np * 16, cb));
                mma8(C.a[0][2*np],   al0, bh[0], bh[1]);
                mma8(C.a[0][2*np+1], al0, bh[2], bh[3]);
                mma8(C.a[1][2*np],   al1, bh[0], bh[1]);
                mma8(C.a[1][2*np+1], al1, bh[2], bh[3]);
                mma8(C.a[0][2*np],   ah0, bl[0], bl[1]);
                mma8(C.a[0][2*np+1], ah0, bl[2], bl[3]);
                mma8(C.a[1][2*np],   ah1, bl[0], bl[1]);
                mma8(C.a[1][2*np+1], ah1, bl[2], bl[3]);
            }
        }
        __syncthreads();
    }
}

// ======================= QKV GEMM kernel: CTA 128(m) x 64(one head) =======================
// Q,K: fp8 cross pass (2^11-scaled) then x2^-11, then fp16 hi pass.  V: fp16 only.
__global__ __launch_bounds__(256, 2) void qkv_mma_kernel(
    const float* __restrict__ bq, const float* __restrict__ bk, const float* __restrict__ bv)
{
    extern __shared__ __align__(16) char smem[];
    const uint32_t sb = smem_u32(smem);
    const int t = threadIdx.x, lane = t & 31, wid = t >> 5;
    const int m0 = blockIdx.x * 128;
    const int zz = blockIdx.y;             // 0..35
    const int which = zz / H;
    const int h = zz % H;

    Acc64 C;
    #pragma unroll
    for (int i = 0; i < 2; i++)
        #pragma unroll
        for (int j = 0; j < 4; j++)
            C.a[i][j][0] = C.a[i][j][1] = C.a[i][j][2] = C.a[i][j][3] = 0.f;

    const size_t woff = ((size_t)which * H + h) * E * D;

    if (which != 2) {
        gemm_fp8_pass(g_x_h8 + (size_t)m0 * D, g_x_l8 + (size_t)m0 * D,
                      g_wt_h8 + woff, g_wt_l8 + woff, D, D, sb, t, C);
        #pragma unroll
        for (int i = 0; i < 2; i++)
            #pragma unroll
            for (int j = 0; j < 4; j++) {
                C.a[i][j][0] *= LO_UNSCALE; C.a[i][j][1] *= LO_UNSCALE;
                C.a[i][j][2] *= LO_UNSCALE; C.a[i][j][3] *= LO_UNSCALE;
            }
    }
    gemm_fp16_pass(g_x_hi + (size_t)m0 * D, g_wt_hi + woff, D, D, sb, t, C);

    const float* bias = (which == 0) ? bq : (which == 1) ? bk : bv;
    const int g = lane >> 2, j2 = (lane & 3) * 2;
    const int wm = (wid >> 1) * 32, wn = (wid & 1) * 32;
    const size_t obase = ((size_t)which * H + h) * BS * E;
    const size_t o8base = (size_t)h * BS * E;

    #pragma unroll
    for (int mi = 0; mi < 2; mi++) {
        #pragma unroll
        for (int half2i = 0; half2i < 2; half2i++) {
            const int mA = m0 + wm + mi * 16 + g + half2i * 8;
            #pragma unroll
            for (int nt = 0; nt < 4; nt++) {
                const int e = wn + nt * 8 + j2;
                const float b0f = bias[h * E + e], b1f = bias[h * E + e + 1];
                const float v0 = C.a[mi][nt][half2i * 2 + 0] + b0f;
                const float v1 = C.a[mi][nt][half2i * 2 + 1] + b1f;
                const uint32_t hp = pack2(v0, v1);
                *(uint32_t*)(g_qkvb_hi + obase + (size_t)mA * E + e) = hp;
                if (which == 0) {
                    *(uint16_t*)(g_q8 + o8base + (size_t)mA * E + e) = cvt2e4m3(v0, v1);
                } else if (which == 1) {
                    __half2 hh = *(__half2*)&hp;
                    *(uint16_t*)(g_kl8 + o8base + (size_t)mA * E + e) =
                        cvt2e4m3((v0 - __low2float(hh)) * LO_SCALE,
                                 (v1 - __high2float(hh)) * LO_SCALE);
                }
            }
        }
    }
}

// ======================= output projection: CTA 128(m) x 64(n), fp16 1-product ==========
__global__ __launch_bounds__(256, 2) void proj_mma_kernel(
    const float* __restrict__ bo, float* __restrict__ out)
{
    extern __shared__ __align__(16) char smem[];
    const uint32_t sb = smem_u32(smem);
    const int t = threadIdx.x, lane = t & 31, wid = t >> 5;
    const int m0 = blockIdx.x * 128;
    const int n0 = blockIdx.y * 64;

    Acc64 C;
    #pragma unroll
    for (int i = 0; i < 2; i++)
        #pragma unroll
        for (int j = 0; j < 4; j++)
            C.a[i][j][0] = C.a[i][j][1] = C.a[i][j][2] = C.a[i][j][3] = 0.f;

    gemm_fp16_pass(g_att_hi + (size_t)m0 * D, g_wo_hi + (size_t)n0 * D, D, D, sb, t, C);

    const int g = lane >> 2, j2 = (lane & 3) * 2;
    const int wm = (wid >> 1) * 32, wn = (wid & 1) * 32;

    #pragma unroll
    for (int mi = 0; mi < 2; mi++) {
        const int mA = m0 + wm + mi * 16 + g;
        #pragma unroll
        for (int nt = 0; nt < 4; nt++) {
            const int n = n0 + wn + nt * 8 + j2;
            const float b0f = bo[n], b1f = bo[n + 1];
            float2 v0 = { C.a[mi][nt][0] + b0f, C.a[mi][nt][1] + b1f };
            float2 v1 = { C.a[mi][nt][2] + b0f, C.a[mi][nt][3] + b1f };
            *(float2*)(out + (size_t)mA * D + n) = v0;
            *(float2*)(out + (size_t)(mA + 8) * D + n) = v1;
        }
    }
}

// ======================= flash attention =======================
// 256 threads, 8 warps x 16 q-rows; kv chunks of 64, 32 chunks.
// S = mask + qh*kh (fp16) + q8*kl8 (fp8, 2^11-scaled): s init = mask*2^11,
// fp8 MMAs accumulate scaled, then s *= 2^-11, then fp16 hi MMAs.  PV fp16 1-product.
#define A_KV    24576   // resident: Qh fp16 16K + Q8 fp8 8K
#define A_STAGE 20480   // Kh 8K + Vh 8K + Kl8 4K
__global__ __launch_bounds__(256, 2) void attn_kernel(const float* __restrict__ mask_all)
{
    extern __shared__ __align__(16) char smem[];
    const uint32_t sb = smem_u32(smem);

    const int q0 = blockIdx.x * 128;
    const int hb = blockIdx.y;
    const int h = hb / B, b = hb % B;

    const __half*  Qh_g = g_qkvb_hi + ((size_t)0 * H + h) * BS * E + (size_t)(b * S + q0) * E;
    const uint8_t* Q8_g = g_q8 + (size_t)h * BS * E + (size_t)(b * S + q0) * E;
    const __half*  Kh_g = g_qkvb_hi + ((size_t)1 * H + h) * BS * E + (size_t)b * S * E;
    const uint8_t* K8_g = g_kl8 + (size_t)h * BS * E + (size_t)b * S * E;
    const __half*  Vh_g = g_qkvb_hi + ((size_t)2 * H + h) * BS * E + (size_t)b * S * E;
    const float* mask = mask_all + (size_t)(h * B + b) * S * S;

    const int t = threadIdx.x, lane = t & 31, wid = t >> 5;
    const int g = lane >> 2, j2 = (lane & 3) * 2;
    const int r0 = wid * 16;

    // resident Q (fp16 + fp8)
    cpa_tile<128>(Qh_g, E, sb, t);
    cpa_tile8<128>(Q8_g, E, sb + 16384, t);
    CP_COMMIT();
    // kv chunk 0 -> stage 0
    cpa_tile<64>(Kh_g, E, sb + A_KV, t);
    cpa_tile<64>(Vh_g, E, sb + A_KV + 8192, t);
    cpa_tile8<64>(K8_g, E, sb + A_KV + 16384, t);
    CP_COMMIT();

    float m_a = -INFINITY, m_b = -INFINITY, l_a = 0.f, l_b = 0.f;
    float o[8][4];
    #pragma unroll
    for (int et = 0; et < 8; et++)
        o[et][0] = o[et][1] = o[et][2] = o[et][3] = 0.f;

    const uint32_t a_row  = (uint32_t)(r0 + (lane & 15));
    const uint32_t a_chi  = (uint32_t)((lane >> 4) & 1);
    const uint32_t b_row0 = (uint32_t)((lane & 7) + ((lane & 16) >> 1));
    const uint32_t b_chi  = (uint32_t)((lane >> 3) & 1);
    const uint32_t v_row  = (uint32_t)(lane & 15);
    const uint32_t v_chi  = (uint32_t)((lane >> 4) & 1);

    #pragma unroll 1
    for (int jc = 0; jc < 32; jc++) {
        const int j0 = jc * 64;

        // mask loads (scaled by 2^11) initialize S accumulators; overlap pipeline wait
        float s[8][4];
        const float* mra = mask + (size_t)(q0 + r0 + g) * S + j0 + j2;
        const float* mrb = mra + 8 * S;
        #pragma unroll
        for (int nt = 0; nt < 8; nt++) {
            float2 ma = *(const float2*)(mra + nt * 8);
            float2 mb = *(const float2*)(mrb + nt * 8);
            s[nt][0] = ma.x * LO_SCALE; s[nt][1] = ma.y * LO_SCALE;
            s[nt][2] = mb.x * LO_SCALE; s[nt][3] = mb.y * LO_SCALE;
        }

        if (jc + 1 < 32) {
            const uint32_t ns = sb + A_KV + (uint32_t)((jc + 1) & 1) * A_STAGE;
            const size_t go = (size_t)(j0 + 64) * E;
            cpa_tile<64>(Kh_g + go, E, ns, t);
            cpa_tile<64>(Vh_g + go, E, ns + 8192, t);
            cpa_tile8<64>(K8_g + go, E, ns + 16384, t);
            CP_COMMIT();
            CP_WAIT1();
        } else {
            CP_WAIT0();
        }
        __syncthreads();

        const uint32_t cs = sb + A_KV + (uint32_t)(jc & 1) * A_STAGE;
        const uint32_t uKh = cs, uVh = cs + 8192, uK8 = cs + 16384;

        // ---- fp8 cross: s += 2^11 * (q * k_lo)  (2 k32 steps over E=64) ----
        #pragma unroll
        for (int ks = 0; ks < 2; ks++) {
            const uint32_t ca = (uint32_t)(ks * 2) + a_chi;
            const uint32_t cb = (uint32_t)(ks * 2) + b_chi;
            uint32_t q8f[4];
            ldsm4(q8f, sb + 16384 + sw8_off(a_row, ca));
            #pragma unroll
            for (int np = 0; np < 4; np++) {
                uint32_t kb[4];
                ldsm4(kb, uK8 + sw8_off(b_row0 + np * 16, cb));
                mma8(s[2*np],   q8f, kb[0], kb[1]);
                mma8(s[2*np+1], q8f, kb[2], kb[3]);
            }
        }
        // unscale: s = mask + q*k_lo
        #pragma unroll
        for (int nt = 0; nt < 8; nt++) {
            s[nt][0] *= LO_UNSCALE; s[nt][1] *= LO_UNSCALE;
            s[nt][2] *= LO_UNSCALE; s[nt][3] *= LO_UNSCALE;
        }

        // ---- fp16 hi: s += qh * kh ----
        #pragma unroll
        for (int ks = 0; ks < 4; ks++) {
            const uint32_t c16a = (uint32_t)(ks * 2) + a_chi;
            const uint32_t c16b = (uint32_t)(ks * 2) + b_chi;
            uint32_t qh[4];
            ldsm4(qh, sb + sw_off(a_row, c16a));
            #pragma unroll
            for (int np = 0; np < 4; np++) {
                uint32_t bh[4];
                ldsm4(bh, uKh + sw_off(b_row0 + np * 16, c16b));
                mma16816(s[2*np],   qh, bh[0], bh[1]);
                mma16816(s[2*np+1], qh, bh[2], bh[3]);
            }
        }

        // ---- online softmax (rows g and g+8) ----
        float mxa = -INFINITY, mxb = -INFINITY;
        #pragma unroll
        for (int nt = 0; nt < 8; nt++) {
            mxa = fmaxf(mxa, fmaxf(s[nt][0], s[nt][1]));
            mxb = fmaxf(mxb, fmaxf(s[nt][2], s[nt][3]));
        }
        mxa = fmaxf(mxa, __shfl_xor_sync(0xffffffffu, mxa, 1));
        mxa = fmaxf(mxa, __shfl_xor_sync(0xffffffffu, mxa, 2));
        mxb = fmaxf(mxb, __shfl_xor_sync(0xffffffffu, mxb, 1));
        mxb = fmaxf(mxb, __shfl_xor_sync(0xffffffffu, mxb, 2));

        const float mna = fmaxf(m_a, mxa), mnb = fmaxf(m_b, mxb);
        const float aa = __expf(m_a - mna), ab = __expf(m_b - mnb);
        float sa = 0.f, sb2 = 0.f;
        #pragma unroll
        for (int nt = 0; nt < 8; nt++) {
            s[nt][0] = __expf(s[nt][0] - mna); sa += s[nt][0];
            s[nt][1] = __expf(s[nt][1] - mna); sa += s[nt][1];
            s[nt][2] = __expf(s[nt][2] - mnb); sb2 += s[nt][2];
            s[nt][3] = __expf(s[nt][3] - mnb); sb2 += s[nt][3];
        }
        sa  += __shfl_xor_sync(0xffffffffu, sa, 1);
        sa  += __shfl_xor_sync(0xffffffffu, sa, 2);
        sb2 += __shfl_xor_sync(0xffffffffu, sb2, 1);
        sb2 += __shfl_xor_sync(0xffffffffu, sb2, 2);
        l_a = l_a * aa + sa; l_b = l_b * ab + sb2;
        m_a = mna; m_b = mnb;
        #pragma unroll
        for (int et = 0; et < 8; et++) {
            o[et][0] *= aa; o[et][1] *= aa;
            o[et][2] *= ab; o[et][3] *= ab;
        }

        // ---- O += P V (P plain fp16) ----
        #pragma unroll
        for (int ks2 = 0; ks2 < 4; ks2++) {
            const int nt0 = 2 * ks2, nt1 = nt0 + 1;
            uint32_t a_p[4];
            a_p[0] = pack2(s[nt0][0], s[nt0][1]);
            a_p[1] = pack2(s[nt0][2], s[nt0][3]);
            a_p[2] = pack2(s[nt1][0], s[nt1][1]);
            a_p[3] = pack2(s[nt1][2], s[nt1][3]);
            #pragma unroll
            for (int ep = 0; ep < 4; ep++) {
                uint32_t vh[4];
                ldsm4t(vh, uVh + sw_off(v_row + ks2 * 16, (uint32_t)(ep * 2) + v_chi));
                mma16816(o[2*ep],   a_p, vh[0], vh[1]);
                mma16816(o[2*ep+1], a_p, vh[2], vh[3]);
            }
        }
        __syncthreads();
    }

    // ---- epilogue: normalize, pack fp16, concat-head layout ----
    const float ia = 1.f / l_a, ib = 1.f / l_b;
    const int rowA = q0 + r0 + g, rowB = rowA + 8;
    #pragma unroll
    for (int et = 0; et < 8; et++) {
        const size_t col = (size_t)h * E + et * 8 + j2;
        *(uint32_t*)(g_att_hi + (size_t)(b * S + rowA) * D + col) =
            pack2(o[et][0] * ia, o[et][1] * ia);
        *(uint32_t*)(g_att_hi + (size_t)(b * S + rowB) * D + col) =
            pack2(o[et][2] * ib, o[et][3] * ib);
    }
}

// ======================= Launch =======================
extern "C" void kernel_launch(void* const* d_in, const int* in_sizes, int n_in,
                              void* d_out, int out_size)
{
    const float* x    = (const float*)d_in[0];
    const float* mask = (const float*)d_in[1];
    const float* Wq   = (const float*)d_in[2];
    const float* bq   = (const float*)d_in[3];
    const float* Wk   = (const float*)d_in[4];
    const float* bk   = (const float*)d_in[5];
    const float* Wv   = (const float*)d_in[6];
    const float* bv   = (const float*)d_in[7];
    const float* Wo   = (const float*)d_in[8];
    const float* bo   = (const float*)d_in[9];

    const int smem_gemm = 2 * G_STAGE;          // 49,152 B
    const int smem_attn = A_KV + 2 * A_STAGE;   // 65,536 B
    cudaFuncSetAttribute(qkv_mma_kernel,  cudaFuncAttributeMaxDynamicSharedMemorySize, smem_gemm);
    cudaFuncSetAttribute(proj_mma_kernel, cudaFuncAttributeMaxDynamicSharedMemorySize, smem_gemm);
    cudaFuncSetAttribute(attn_kernel,     cudaFuncAttributeMaxDynamicSharedMemorySize, smem_attn);

    const int prep_n = (XN + 3 * HED + D * D) / 2;
    prep_kernel<<< (prep_n + 255) / 256, 256 >>>(x, Wq, Wk, Wv, Wo);

    qkv_mma_kernel <<< dim3(BS / 128, 3 * H), 256, smem_gemm >>>(bq, bk, bv);
    attn_kernel    <<< dim3(S / 128, H * B), 256, smem_attn >>>(mask);
    proj_mma_kernel<<< dim3(BS / 128, D / 64), 256, smem_gemm >>>(bo, (float*)d_out);
}

// round 13
// speedup vs baseline: 1.1164x; 1.1164x over previous
#include <cuda_runtime.h>
#include <cuda_fp16.h>
#include <math.h>
#include <stdint.h>

#define B 2
#define S 2048
#define D 768
#define H 12
#define E 64
#define BS (B*S)   // 4096
#define XN (BS*D)
#define HED (H*E*D)

// ---- scratch (static device globals; no runtime allocation) ----
__device__ __align__(16) __half g_x_hi[(size_t)BS * D];
__device__ __align__(16) __half g_x_lo[(size_t)BS * D];
__device__ __align__(16) __half g_wt_hi[(size_t)3 * HED];     // [which][h*E+e][k]
__device__ __align__(16) __half g_wt_lo[(size_t)3 * HED];
__device__ __align__(16) __half g_wo_hi[(size_t)D * D];       // [n][k]
__device__ __align__(16) __half g_qkvb_hi[(size_t)3 * H * BS * E]; // [which][h][b*S+s][e]
__device__ __align__(16) __half g_qkvb_lo[(size_t)3 * H * BS * E]; // only K-lo used
__device__ __align__(16) __half g_att_hi[(size_t)BS * D];     // [b*S+s][h*E+e]

// ======================= helpers =======================
__device__ __forceinline__ uint32_t smem_u32(const void* p) {
    uint32_t a;
    asm("{ .reg .u64 t; cvta.to.shared.u64 t, %1; cvt.u32.u64 %0, t; }" : "=r"(a) : "l"(p));
    return a;
}
// swizzled offset within a tile of 128-byte rows: row r, 16B-chunk c16 (0..7)
__device__ __forceinline__ uint32_t sw_off(uint32_t r, uint32_t c16) {
    return (r << 7) + (((c16 ^ r) & 7u) << 4);
}
__device__ __forceinline__ void ldsm4(uint32_t* r, uint32_t a) {
    asm volatile("ldmatrix.sync.aligned.m8n8.x4.shared.b16 {%0,%1,%2,%3}, [%4];"
        : "=r"(r[0]), "=r"(r[1]), "=r"(r[2]), "=r"(r[3]) : "r"(a));
}
__device__ __forceinline__ void ldsm4t(uint32_t* r, uint32_t a) {
    asm volatile("ldmatrix.sync.aligned.m8n8.x4.trans.shared.b16 {%0,%1,%2,%3}, [%4];"
        : "=r"(r[0]), "=r"(r[1]), "=r"(r[2]), "=r"(r[3]) : "r"(a));
}
__device__ __forceinline__ void mma16816(float* c, const uint32_t* a, uint32_t b0, uint32_t b1) {
    asm volatile("mma.sync.aligned.m16n8k16.row.col.f32.f16.f16.f32 "
        "{%0,%1,%2,%3}, {%4,%5,%6,%7}, {%8,%9}, {%0,%1,%2,%3};"
        : "+f"(c[0]), "+f"(c[1]), "+f"(c[2]), "+f"(c[3])
        : "r"(a[0]), "r"(a[1]), "r"(a[2]), "r"(a[3]), "r"(b0), "r"(b1));
}
__device__ __forceinline__ void split2(float x, float y, uint32_t& hi, uint32_t& lo) {
    __half2 h = __floats2half2_rn(x, y);
    float hx = __low2float(h), hy = __high2float(h);
    __half2 l = __floats2half2_rn(x - hx, y - hy);
    hi = *(uint32_t*)&h; lo = *(uint32_t*)&l;
}
__device__ __forceinline__ uint32_t pack2(float x, float y) {
    __half2 h = __floats2half2_rn(x, y);
    return *(uint32_t*)&h;
}
#define CP_COMMIT()  asm volatile("cp.async.commit_group;" ::: "memory")
#define CP_WAIT1()   asm volatile("cp.async.wait_group 1;" ::: "memory")
#define CP_WAIT0()   asm volatile("cp.async.wait_group 0;" ::: "memory")

// cp.async R rows x 64 fp16 (128B/row) -> swizzled smem, NT threads
template<int R, int NT>
__device__ __forceinline__ void cpa_tile(const __half* __restrict__ g, int ldg,
                                         uint32_t sdst, int t)
{
    #pragma unroll
    for (int i = 0; i < (R * 8) / NT; i++) {
        int f = i * NT + t;
        uint32_t r = (uint32_t)(f >> 3), c = (uint32_t)(f & 7);
        asm volatile("cp.async.cg.shared.global [%0], [%1], 16;"
            :: "r"(sdst + sw_off(r, c)), "l"(g + (size_t)r * ldg + c * 8));
    }
}

// ======================= fused prep: fp32 -> fp16 hi/lo =======================
__global__ void prep_kernel(const float* __restrict__ x,
                            const float* __restrict__ Wq, const float* __restrict__ Wk,
                            const float* __restrict__ Wv, const float* __restrict__ Wo)
{
    int i = blockIdx.x * 256 + threadIdx.x;
    float v;
    if (i < XN) {
        v = x[i];
        __half hv = __float2half_rn(v);
        g_x_hi[i] = hv;
        g_x_lo[i] = __float2half_rn(v - __half2float(hv));
    } else if (i < XN + 3 * HED) {
        int i2 = i - XN;
        int w = i2 / HED, r2 = i2 % HED;
        int k = r2 % D, row = r2 / D;
        int h = row / E, e = row % E;
        const float* W = (w == 0) ? Wq : (w == 1) ? Wk : Wv;
        v = W[((size_t)h * D + k) * E + e];
        __half hv = __float2half_rn(v);
        g_wt_hi[i2] = hv;
        g_wt_lo[i2] = __float2half_rn(v - __half2float(hv));
    } else if (i < XN + 3 * HED + D * D) {
        int i3 = i - XN - 3 * HED;
        int k = i3 % D, n = i3 / D;
        g_wo_hi[i3] = __float2half_rn(Wo[(size_t)k * D + n]);
    }
}

// ======================= GEMM core: CTA 128x64, 8 warps (4x2), warp tile 32x32 ==========
// products: Ah*Bh always; + Al*Bh if use_alo; + Ah*Bl if use_blo. hi/alo/blo passes.
struct Acc64 { float a[2][4][4]; };
#define G_STAGE 49152

__device__ __forceinline__ void gemm_core(
    const __half* __restrict__ Ah_g, const __half* __restrict__ Al_g, int lda,
    const __half* __restrict__ Bh_g, const __half* __restrict__ Bl_g, int ldb,
    uint32_t sb, int t, Acc64& C, bool use_alo, bool use_blo)
{
    const int lane = t & 31, wid = t >> 5;
    const int wm = (wid >> 1) * 32, wn = (wid & 1) * 32;

    cpa_tile<128, 256>(Ah_g, lda, sb, t);
    if (use_alo) cpa_tile<128, 256>(Al_g, lda, sb + 16384, t);
    cpa_tile<64, 256>(Bh_g, ldb, sb + 32768, t);
    if (use_blo) cpa_tile<64, 256>(Bl_g, ldb, sb + 40960, t);
    CP_COMMIT();

    const uint32_t a_row  = (uint32_t)(wm + (lane & 15));
    const uint32_t a_chi  = (uint32_t)((lane >> 4) & 1);
    const uint32_t b_row0 = (uint32_t)(wn + (lane & 7) + ((lane & 16) >> 1));
    const uint32_t b_chi  = (uint32_t)((lane >> 3) & 1);

    #pragma unroll 1
    for (int c = 0; c < 12; c++) {
        if (c + 1 < 12) {
            uint32_t st = sb + (uint32_t)((c + 1) & 1) * G_STAGE;
            cpa_tile<128, 256>(Ah_g + (c + 1) * 64, lda, st, t);
            if (use_alo) cpa_tile<128, 256>(Al_g + (c + 1) * 64, lda, st + 16384, t);
            cpa_tile<64, 256>(Bh_g + (c + 1) * 64, ldb, st + 32768, t);
            if (use_blo) cpa_tile<64, 256>(Bl_g + (c + 1) * 64, ldb, st + 40960, t);
            CP_COMMIT();
            CP_WAIT1();
        } else {
            CP_WAIT0();
        }
        __syncthreads();

        const uint32_t cs = sb + (uint32_t)(c & 1) * G_STAGE;
        const uint32_t uAh = cs, uAl = cs + 16384, uBh = cs + 32768, uBl = cs + 40960;

        #pragma unroll
        for (int ks = 0; ks < 4; ks++) {
            const uint32_t c16a = (uint32_t)(ks * 2) + a_chi;
            const uint32_t c16b = (uint32_t)(ks * 2) + b_chi;
            uint32_t ah0[4], ah1[4], bh0[4], bh1[4];
            ldsm4(ah0, uAh + sw_off(a_row, c16a));
            ldsm4(ah1, uAh + sw_off(a_row + 16, c16a));
            ldsm4(bh0, uBh + sw_off(b_row0, c16b));
            ldsm4(bh1, uBh + sw_off(b_row0 + 16, c16b));
            mma16816(C.a[0][0], ah0, bh0[0], bh0[1]);
            mma16816(C.a[0][1], ah0, bh0[2], bh0[3]);
            mma16816(C.a[1][0], ah1, bh0[0], bh0[1]);
            mma16816(C.a[1][1], ah1, bh0[2], bh0[3]);
            mma16816(C.a[0][2], ah0, bh1[0], bh1[1]);
            mma16816(C.a[0][3], ah0, bh1[2], bh1[3]);
            mma16816(C.a[1][2], ah1, bh1[0], bh1[1]);
            mma16816(C.a[1][3], ah1, bh1[2], bh1[3]);
            if (use_alo) {
                uint32_t al0[4], al1[4];
                ldsm4(al0, uAl + sw_off(a_row, c16a));
                ldsm4(al1, uAl + sw_off(a_row + 16, c16a));
                mma16816(C.a[0][0], al0, bh0[0], bh0[1]);
                mma16816(C.a[0][1], al0, bh0[2], bh0[3]);
                mma16816(C.a[1][0], al1, bh0[0], bh0[1]);
                mma16816(C.a[1][1], al1, bh0[2], bh0[3]);
                mma16816(C.a[0][2], al0, bh1[0], bh1[1]);
                mma16816(C.a[0][3], al0, bh1[2], bh1[3]);
                mma16816(C.a[1][2], al1, bh1[0], bh1[1]);
                mma16816(C.a[1][3], al1, bh1[2], bh1[3]);
            }
            if (use_blo) {
                uint32_t bl0[4], bl1[4];
                ldsm4(bl0, uBl + sw_off(b_row0, c16b));
                ldsm4(bl1, uBl + sw_off(b_row0 + 16, c16b));
                mma16816(C.a[0][0], ah0, bl0[0], bl0[1]);
                mma16816(C.a[0][1], ah0, bl0[2], bl0[3]);
                mma16816(C.a[1][0], ah1, bl0[0], bl0[1]);
                mma16816(C.a[1][1], ah1, bl0[2], bl0[3]);
                mma16816(C.a[0][2], ah0, bl1[0], bl1[1]);
                mma16816(C.a[0][3], ah0, bl1[2], bl1[3]);
                mma16816(C.a[1][2], ah1, bl1[0], bl1[1]);
                mma16816(C.a[1][3], ah1, bl1[2], bl1[3]);
            }
        }
        __syncthreads();
    }
}

// ======================= QKV GEMM kernel: CTA 128(m) x 64(one head) =======================
// Q: 2-product (xh*Wh + xl*Wh).  K: 3-product.  V: 1-product.
__global__ __launch_bounds__(256, 2) void qkv_mma_kernel(
    const float* __restrict__ bq, const float* __restrict__ bk, const float* __restrict__ bv)
{
    extern __shared__ __align__(16) char smem[];
    const uint32_t sb = smem_u32(smem);
    const int t = threadIdx.x, lane = t & 31, wid = t >> 5;
    const int m0 = blockIdx.x * 128;
    const int zz = blockIdx.y;             // 0..35
    const int which = zz / H;
    const int h = zz % H;

    Acc64 C;
    #pragma unroll
    for (int i = 0; i < 2; i++)
        #pragma unroll
        for (int j = 0; j < 4; j++)
            C.a[i][j][0] = C.a[i][j][1] = C.a[i][j][2] = C.a[i][j][3] = 0.f;

    const bool alo = (which != 2);         // Q,K use x_lo
    const bool blo = (which == 1);         // only K uses W_lo
    gemm_core(g_x_hi + (size_t)m0 * D, g_x_lo + (size_t)m0 * D, D,
              g_wt_hi + ((size_t)which * H + h) * E * D,
              g_wt_lo + ((size_t)which * H + h) * E * D, D,
              sb, t, C, alo, blo);

    const float* bias = (which == 0) ? bq : (which == 1) ? bk : bv;
    const int g = lane >> 2, j2 = (lane & 3) * 2;
    const int wm = (wid >> 1) * 32, wn = (wid & 1) * 32;
    const size_t obase = ((size_t)which * H + h) * BS * E;
    const bool need_lo = (which == 1);     // only K-lo is consumed (QK^T 2-product)

    #pragma unroll
    for (int mi = 0; mi < 2; mi++) {
        const int mA = m0 + wm + mi * 16 + g;
        #pragma unroll
        for (int nt = 0; nt < 4; nt++) {
            const int e = wn + nt * 8 + j2;
            const float b0f = bias[h * E + e], b1f = bias[h * E + e + 1];
            uint32_t hi, lo;
            split2(C.a[mi][nt][0] + b0f, C.a[mi][nt][1] + b1f, hi, lo);
            *(uint32_t*)(g_qkvb_hi + obase + (size_t)mA * E + e) = hi;
            if (need_lo) *(uint32_t*)(g_qkvb_lo + obase + (size_t)mA * E + e) = lo;
            split2(C.a[mi][nt][2] + b0f, C.a[mi][nt][3] + b1f, hi, lo);
            *(uint32_t*)(g_qkvb_hi + obase + (size_t)(mA + 8) * E + e) = hi;
            if (need_lo) *(uint32_t*)(g_qkvb_lo + obase + (size_t)(mA + 8) * E + e) = lo;
        }
    }
}

// ======================= output projection: CTA 128(m) x 64(n), 1-product ===============
__global__ __launch_bounds__(256, 2) void proj_mma_kernel(
    const float* __restrict__ bo, float* __restrict__ out)
{
    extern __shared__ __align__(16) char smem[];
    const uint32_t sb = smem_u32(smem);
    const int t = threadIdx.x, lane = t & 31, wid = t >> 5;
    const int m0 = blockIdx.x * 128;
    const int n0 = blockIdx.y * 64;

    Acc64 C;
    #pragma unroll
    for (int i = 0; i < 2; i++)
        #pragma unroll
        for (int j = 0; j < 4; j++)
            C.a[i][j][0] = C.a[i][j][1] = C.a[i][j][2] = C.a[i][j][3] = 0.f;

    gemm_core(g_att_hi + (size_t)m0 * D, g_att_hi + (size_t)m0 * D, D,
              g_wo_hi + (size_t)n0 * D, g_wo_hi + (size_t)n0 * D, D,
              sb, t, C, false, false);

    const int g = lane >> 2, j2 = (lane & 3) * 2;
    const int wm = (wid >> 1) * 32, wn = (wid & 1) * 32;

    #pragma unroll
    for (int mi = 0; mi < 2; mi++) {
        const int mA = m0 + wm + mi * 16 + g;
        #pragma unroll
        for (int nt = 0; nt < 4; nt++) {
            const int n = n0 + wn + nt * 8 + j2;
            const float b0f = bo[n], b1f = bo[n + 1];
            float2 v0 = { C.a[mi][nt][0] + b0f, C.a[mi][nt][1] + b1f };
            float2 v1 = { C.a[mi][nt][2] + b0f, C.a[mi][nt][3] + b1f };
            *(float2*)(out + (size_t)mA * D + n) = v0;
            *(float2*)(out + (size_t)(mA + 8) * D + n) = v1;
        }
    }
}

// ======================= flash attention =======================
// 128 threads, 4 warps x 16 q-rows = 64-row q tile; kv chunks of 64, 32 chunks.
// 4 CTAs/SM to smooth wave-quantization tail.
// S = QK^T 2-product (qh*kh + qh*kl).  PV 1-product (P plain fp16).
#define A_STAGE 24576   // Kh 8K + Kl 8K + Vh 8K
#define A_KV    8192    // resident Qh (64 rows)
__global__ __launch_bounds__(128, 4) void attn_kernel(const float* __restrict__ mask_all)
{
    extern __shared__ __align__(16) char smem[];
    const uint32_t sb = smem_u32(smem);

    const int q0 = blockIdx.x * 64;
    const int hb = blockIdx.y;
    const int h = hb / B, b = hb % B;

    const __half* Qh_g = g_qkvb_hi + ((size_t)0 * H + h) * BS * E + (size_t)(b * S + q0) * E;
    const __half* Kh_g = g_qkvb_hi + ((size_t)1 * H + h) * BS * E + (size_t)b * S * E;
    const __half* Kl_g = g_qkvb_lo + ((size_t)1 * H + h) * BS * E + (size_t)b * S * E;
    const __half* Vh_g = g_qkvb_hi + ((size_t)2 * H + h) * BS * E + (size_t)b * S * E;
    const float* mask = mask_all + (size_t)(h * B + b) * S * S;

    const int t = threadIdx.x, lane = t & 31, wid = t >> 5;   // wid 0..3
    const int g = lane >> 2, j2 = (lane & 3) * 2;
    const int r0 = wid * 16;

    // resident Q (64 rows fp16)
    cpa_tile<64, 128>(Qh_g, E, sb, t);
    CP_COMMIT();
    // kv chunk 0 -> stage 0
    cpa_tile<64, 128>(Kh_g, E, sb + A_KV, t);
    cpa_tile<64, 128>(Kl_g, E, sb + A_KV + 8192, t);
    cpa_tile<64, 128>(Vh_g, E, sb + A_KV + 16384, t);
    CP_COMMIT();

    float m_a = -INFINITY, m_b = -INFINITY, l_a = 0.f, l_b = 0.f;
    float o[8][4];
    #pragma unroll
    for (int et = 0; et < 8; et++)
        o[et][0] = o[et][1] = o[et][2] = o[et][3] = 0.f;

    const uint32_t a_row  = (uint32_t)(r0 + (lane & 15));
    const uint32_t a_chi  = (uint32_t)((lane >> 4) & 1);
    const uint32_t b_row0 = (uint32_t)((lane & 7) + ((lane & 16) >> 1));
    const uint32_t b_chi  = (uint32_t)((lane >> 3) & 1);
    const uint32_t v_row  = (uint32_t)(lane & 15);
    const uint32_t v_chi  = (uint32_t)((lane >> 4) & 1);

    #pragma unroll 1
    for (int jc = 0; jc < 32; jc++) {
        const int j0 = jc * 64;

        // mask loads initialize S accumulators; overlap pipeline wait
        float s[8][4];
        const float* mra = mask + (size_t)(q0 + r0 + g) * S + j0 + j2;
        const float* mrb = mra + 8 * S;
        #pragma unroll
        for (int nt = 0; nt < 8; nt++) {
            float2 ma = *(const float2*)(mra + nt * 8);
            float2 mb = *(const float2*)(mrb + nt * 8);
            s[nt][0] = ma.x; s[nt][1] = ma.y; s[nt][2] = mb.x; s[nt][3] = mb.y;
        }

        if (jc + 1 < 32) {
            const uint32_t ns = sb + A_KV + (uint32_t)((jc + 1) & 1) * A_STAGE;
            const size_t go = (size_t)(j0 + 64) * E;
            cpa_tile<64, 128>(Kh_g + go, E, ns, t);
            cpa_tile<64, 128>(Kl_g + go, E, ns + 8192, t);
            cpa_tile<64, 128>(Vh_g + go, E, ns + 16384, t);
            CP_COMMIT();
            CP_WAIT1();
        } else {
            CP_WAIT0();
        }
        __syncthreads();

        const uint32_t cs = sb + A_KV + (uint32_t)(jc & 1) * A_STAGE;
        const uint32_t uKh = cs, uKl = cs + 8192, uVh = cs + 16384;

        // ---- S += Q K^T (2-product; hi pass then lo pass) ----
        #pragma unroll
        for (int ks = 0; ks < 4; ks++) {
            const uint32_t c16a = (uint32_t)(ks * 2) + a_chi;
            const uint32_t c16b = (uint32_t)(ks * 2) + b_chi;
            uint32_t qh[4];
            ldsm4(qh, sb + sw_off(a_row, c16a));
            #pragma unroll
            for (int np = 0; np < 4; np++) {
                uint32_t bh[4];
                ldsm4(bh, uKh + sw_off(b_row0 + np * 16, c16b));
                mma16816(s[2*np],   qh, bh[0], bh[1]);
                mma16816(s[2*np+1], qh, bh[2], bh[3]);
            }
            #pragma unroll
            for (int np = 0; np < 4; np++) {
                uint32_t bl[4];
                ldsm4(bl, uKl + sw_off(b_row0 + np * 16, c16b));
                mma16816(s[2*np],   qh, bl[0], bl[1]);
                mma16816(s[2*np+1], qh, bl[2], bl[3]);
            }
        }

        // ---- online softmax (rows g and g+8) ----
        float mxa = -INFINITY, mxb = -INFINITY;
        #pragma unroll
        for (int nt = 0; nt < 8; nt++) {
            mxa = fmaxf(mxa, fmaxf(s[nt][0], s[nt][1]));
            mxb = fmaxf(mxb, fmaxf(s[nt][2], s[nt][3]));
        }
        mxa = fmaxf(mxa, __shfl_xor_sync(0xffffffffu, mxa, 1));
        mxa = fmaxf(mxa, __shfl_xor_sync(0xffffffffu, mxa, 2));
        mxb = fmaxf(mxb, __shfl_xor_sync(0xffffffffu, mxb, 1));
        mxb = fmaxf(mxb, __shfl_xor_sync(0xffffffffu, mxb, 2));

        const float mna = fmaxf(m_a, mxa), mnb = fmaxf(m_b, mxb);
        const float aa = __expf(m_a - mna), ab = __expf(m_b - mnb);
        float sa = 0.f, sb2 = 0.f;
        #pragma unroll
        for (int nt = 0; nt < 8; nt++) {
            s[nt][0] = __expf(s[nt][0] - mna); sa += s[nt][0];
            s[nt][1] = __expf(s[nt][1] - mna); sa += s[nt][1];
            s[nt][2] = __expf(s[nt][2] - mnb); sb2 += s[nt][2];
            s[nt][3] = __expf(s[nt][3] - mnb); sb2 += s[nt][3];
        }
        sa  += __shfl_xor_sync(0xffffffffu, sa, 1);
        sa  += __shfl_xor_sync(0xffffffffu, sa, 2);
        sb2 += __shfl_xor_sync(0xffffffffu, sb2, 1);
        sb2 += __shfl_xor_sync(0xffffffffu, sb2, 2);
        l_a = l_a * aa + sa; l_b = l_b * ab + sb2;
        m_a = mna; m_b = mnb;
        #pragma unroll
        for (int et = 0; et < 8; et++) {
            o[et][0] *= aa; o[et][1] *= aa;
            o[et][2] *= ab; o[et][3] *= ab;
        }

        // ---- O += P V (P plain fp16: 1-product) ----
        #pragma unroll
        for (int ks2 = 0; ks2 < 4; ks2++) {
            const int nt0 = 2 * ks2, nt1 = nt0 + 1;
            uint32_t a_p[4];
            a_p[0] = pack2(s[nt0][0], s[nt0][1]);
            a_p[1] = pack2(s[nt0][2], s[nt0][3]);
            a_p[2] = pack2(s[nt1][0], s[nt1][1]);
            a_p[3] = pack2(s[nt1][2], s[nt1][3]);
            #pragma unroll
            for (int ep = 0; ep < 4; ep++) {
                uint32_t vh[4];
                ldsm4t(vh, uVh + sw_off(v_row + ks2 * 16, (uint32_t)(ep * 2) + v_chi));
                mma16816(o[2*ep],   a_p, vh[0], vh[1]);
                mma16816(o[2*ep+1], a_p, vh[2], vh[3]);
            }
        }
        __syncthreads();
    }

    // ---- epilogue: normalize, pack fp16, concat-head layout ----
    const float ia = 1.f / l_a, ib = 1.f / l_b;
    const int rowA = q0 + r0 + g, rowB = rowA + 8;
    #pragma unroll
    for (int et = 0; et < 8; et++) {
        const size_t col = (size_t)h * E + et * 8 + j2;
        *(uint32_t*)(g_att_hi + (size_t)(b * S + rowA) * D + col) =
            pack2(o[et][0] * ia, o[et][1] * ia);
        *(uint32_t*)(g_att_hi + (size_t)(b * S + rowB) * D + col) =
            pack2(o[et][2] * ib, o[et][3] * ib);
    }
}

// ======================= Launch =======================
extern "C" void kernel_launch(void* const* d_in, const int* in_sizes, int n_in,
                              void* d_out, int out_size)
{
    const float* x    = (const float*)d_in[0];
    const float* mask = (const float*)d_in[1];
    const float* Wq   = (const float*)d_in[2];
    const float* bq   = (const float*)d_in[3];
    const float* Wk   = (const float*)d_in[4];
    const float* bk   = (const float*)d_in[5];
    const float* Wv   = (const float*)d_in[6];
    const float* bv   = (const float*)d_in[7];
    const float* Wo   = (const float*)d_in[8];
    const float* bo   = (const float*)d_in[9];

    const int smem_gemm = 2 * G_STAGE;          // 98,304 B
    const int smem_attn = A_KV + 2 * A_STAGE;   // 57,344 B -> 4 CTAs/SM
    cudaFuncSetAttribute(qkv_mma_kernel,  cudaFuncAttributeMaxDynamicSharedMemorySize, smem_gemm);
    cudaFuncSetAttribute(proj_mma_kernel, cudaFuncAttributeMaxDynamicSharedMemorySize, smem_gemm);
    cudaFuncSetAttribute(attn_kernel,     cudaFuncAttributeMaxDynamicSharedMemorySize, smem_attn);

    const int prep_n = XN + 3 * HED + D * D;
    prep_kernel<<< (prep_n + 255) / 256, 256 >>>(x, Wq, Wk, Wv, Wo);

    qkv_mma_kernel <<< dim3(BS / 128, 3 * H), 256, smem_gemm >>>(bq, bk, bv);
    attn_kernel    <<< dim3(S / 64, H * B), 128, smem_attn >>>(mask);
    proj_mma_kernel<<< dim3(BS / 128, D / 64), 256, smem_gemm >>>(bo, (float*)d_out);
}